// round 1
// baseline (speedup 1.0000x reference)
#include <cuda_runtime.h>
#include <math.h>

// Problem constants
#define BB 1024   // batch
#define DD 512    // feature dim
#define KK 255    // internal nodes
#define LL 256    // leaves
#define CC 80     // leaf output channels

// Leaf-GEMM tiling
#define LPC 4                 // leaves per chunk
#define NCHUNK (LL / LPC)     // 64 leaf chunks
#define MTILES (BB / 128)     // 8 row tiles

// ---------------- device scratch (static, no allocations) ----------------
__device__ float g_ne[KK * DD];                 // normalized node embeddings
__device__ float g_probs[BB * LL];              // leaf probabilities
__device__ float g_partial[NCHUNK * BB * CC];   // split-L partials

// ---------------- K1: row-normalize node embeddings ----------------
__global__ void k_norm(const float* __restrict__ ne) {
    int k = blockIdx.x;          // 0..254
    int t = threadIdx.x;         // 128 threads
    const float* row = ne + (size_t)k * DD;
    float s = 0.f;
    for (int d = t; d < DD; d += 128) { float v = row[d]; s += v * v; }
    __shared__ float red[4];
    #pragma unroll
    for (int o = 16; o > 0; o >>= 1) s += __shfl_xor_sync(0xffffffffu, s, o);
    if ((t & 31) == 0) red[t >> 5] = s;
    __syncthreads();
    float inv = 1.0f / sqrtf(red[0] + red[1] + red[2] + red[3]);
    for (int d = t; d < DD; d += 128) g_ne[(size_t)k * DD + d] = row[d] * inv;
}

// ---------------- K2: node_sim = sigmoid(x @ ne_norm^T), 64x64 tiles ----------------
__global__ void k_nodesim(const float* __restrict__ x, float* __restrict__ out_ns) {
    __shared__ float xt[64 * 32];      // [row][d]
    __shared__ float nt[64 * 36];      // [k][d], padded to 36
    int row0 = blockIdx.x * 64;
    int col0 = blockIdx.y * 64;
    int tid = threadIdx.x;             // 256
    int tx = tid & 15, ty = tid >> 4;
    float acc[4][4] = {};
    for (int dk = 0; dk < 16; ++dk) {
        #pragma unroll
        for (int i = 0; i < 2; ++i) {
            int idx = tid + i * 256;            // float4 index among 512
            int r = idx >> 3, dg = idx & 7;
            float4 v = *(const float4*)(x + (size_t)(row0 + r) * DD + dk * 32 + dg * 4);
            *(float4*)(xt + r * 32 + dg * 4) = v;
        }
        #pragma unroll
        for (int i = 0; i < 2; ++i) {
            int idx = tid + i * 256;
            int r = idx >> 3, dg = idx & 7;
            int kk = col0 + r;
            float4 v = make_float4(0.f, 0.f, 0.f, 0.f);
            if (kk < KK) v = *(const float4*)(g_ne + (size_t)kk * DD + dk * 32 + dg * 4);
            *(float4*)(nt + r * 36 + dg * 4) = v;
        }
        __syncthreads();
        #pragma unroll
        for (int k = 0; k < 32; ++k) {
            float xf[4], nf[4];
            #pragma unroll
            for (int i = 0; i < 4; ++i) xf[i] = xt[(ty * 4 + i) * 32 + k];
            #pragma unroll
            for (int j = 0; j < 4; ++j) nf[j] = nt[(tx + 16 * j) * 36 + k];
            #pragma unroll
            for (int i = 0; i < 4; ++i)
                #pragma unroll
                for (int j = 0; j < 4; ++j) acc[i][j] += xf[i] * nf[j];
        }
        __syncthreads();
    }
    #pragma unroll
    for (int i = 0; i < 4; ++i)
        #pragma unroll
        for (int j = 0; j < 4; ++j) {
            int r = row0 + ty * 4 + i, c = col0 + tx + 16 * j;
            if (c < KK) out_ns[(size_t)r * KK + c] = 1.0f / (1.0f + expf(-acc[i][j]));
        }
}

// ---------------- K3: leaf probabilities via path traversal ----------------
__global__ void k_probs(const float* __restrict__ ns) {
    int b = blockIdx.x;
    int leaf = threadIdx.x;            // 256 threads = 256 leaves
    __shared__ float s[KK];
    if (leaf < KK) s[leaf] = ns[(size_t)b * KK + leaf];
    __syncthreads();
    float p = 1.0f; int node = 0;
    #pragma unroll
    for (int d = 0; d < 8; ++d) {
        int bit = (leaf >> (7 - d)) & 1;
        float v = s[node];
        p *= bit ? (1.0f - v) : v;
        node = 2 * node + 1 + bit;
    }
    g_probs[(size_t)b * LL + leaf] = p;
}

// ---------------- K4: fused leaf GEMM with probs folded into A ----------------
// partial[lch][b][c] = sum over chunk leaves l: probs[b,l]*(x[b,:].W[l,c,:] + bias[l,c])
__global__ void __launch_bounds__(256, 2) k_leaf(const float* __restrict__ x,
                                                 const float* __restrict__ W,
                                                 const float* __restrict__ bias) {
    __shared__ float ps[128 * LPC];    // probs[row][lc]
    __shared__ float bs[LPC * CC];     // bias tile
    __shared__ float xs[128 * 32];     // scaled x tile [row][d]
    __shared__ float ws[80 * 36];      // W tile [c][d], d padded to 36
    int row0 = blockIdx.x * 128;
    int l0 = blockIdx.y * LPC;
    int tid = threadIdx.x;             // 256
    int tx = tid & 15, ty = tid >> 4;

    for (int i = tid; i < 128 * LPC; i += 256) {
        int r = i >> 2, lc = i & (LPC - 1);
        ps[i] = g_probs[(size_t)(row0 + r) * LL + l0 + lc];
    }
    for (int i = tid; i < LPC * CC; i += 256)
        bs[i] = bias[(size_t)l0 * CC + i];

    float acc[8][5] = {};
    for (int lc = 0; lc < LPC; ++lc) {
        const float* Wl = W + (size_t)(l0 + lc) * CC * DD;
        for (int dk = 0; dk < 16; ++dk) {
            __syncthreads();  // protects prior-iter reads + initial ps/bs
            // scaled x tile: 128 rows x 32 d = 1024 float4, 4 per thread
            #pragma unroll
            for (int i = 0; i < 4; ++i) {
                int idx = tid + i * 256;
                int r = idx >> 3, dg = idx & 7;
                float4 v = *(const float4*)(x + (size_t)(row0 + r) * DD + dk * 32 + dg * 4);
                float p = ps[r * LPC + lc];
                v.x *= p; v.y *= p; v.z *= p; v.w *= p;
                *(float4*)(xs + r * 32 + dg * 4) = v;
            }
            // W tile: 80 c x 32 d = 640 float4
            for (int idx = tid; idx < 640; idx += 256) {
                int c = idx >> 3, dg = idx & 7;
                float4 v = *(const float4*)(Wl + (size_t)c * DD + dk * 32 + dg * 4);
                *(float4*)(ws + c * 36 + dg * 4) = v;
            }
            __syncthreads();
            #pragma unroll
            for (int k = 0; k < 32; ++k) {
                float xf[8], wf[5];
                #pragma unroll
                for (int i = 0; i < 8; ++i) xf[i] = xs[(ty * 8 + i) * 32 + k];
                #pragma unroll
                for (int j = 0; j < 5; ++j) wf[j] = ws[(tx + 16 * j) * 36 + k];
                #pragma unroll
                for (int i = 0; i < 8; ++i)
                    #pragma unroll
                    for (int j = 0; j < 5; ++j) acc[i][j] += xf[i] * wf[j];
            }
        }
    }
    // bias epilogue (ps/bs unchanged since load)
    #pragma unroll
    for (int lc = 0; lc < LPC; ++lc)
        #pragma unroll
        for (int i = 0; i < 8; ++i) {
            float p = ps[(ty * 8 + i) * LPC + lc];
            #pragma unroll
            for (int j = 0; j < 5; ++j)
                acc[i][j] += p * bs[lc * CC + tx + 16 * j];
        }
    float* part = g_partial + (size_t)blockIdx.y * BB * CC;
    #pragma unroll
    for (int i = 0; i < 8; ++i)
        #pragma unroll
        for (int j = 0; j < 5; ++j)
            part[(size_t)(row0 + ty * 8 + i) * CC + tx + 16 * j] = acc[i][j];
}

// ---------------- K5: reduce partials over leaf chunks ----------------
__global__ void k_reduce(float* __restrict__ out) {
    int idx = blockIdx.x * 256 + threadIdx.x;   // 81920 total
    float s = 0.f;
    #pragma unroll
    for (int ch = 0; ch < NCHUNK; ++ch)
        s += g_partial[(size_t)ch * BB * CC + idx];
    out[idx] = s;
}

// ---------------- launch ----------------
extern "C" void kernel_launch(void* const* d_in, const int* in_sizes, int n_in,
                              void* d_out, int out_size) {
    const float* x    = (const float*)d_in[0];   // [1024,512]
    const float* ne   = (const float*)d_in[1];   // [255,512]
    const float* W    = (const float*)d_in[2];   // [20480,512]
    const float* bias = (const float*)d_in[3];   // [20480]
    // d_in[4] = res_path (unused; path derived analytically, matches builder)

    float* out1 = (float*)d_out;                 // [1024,80]
    float* ns   = (float*)d_out + BB * CC;       // [1024,255]

    k_norm<<<KK, 128>>>(ne);
    dim3 g2(BB / 64, 4);
    k_nodesim<<<g2, 256>>>(x, ns);
    k_probs<<<BB, 256>>>(ns);
    dim3 g4(MTILES, NCHUNK);
    k_leaf<<<g4, 256>>>(x, W, bias);
    k_reduce<<<(BB * CC) / 256, 256>>>(out1);
}

// round 3
// speedup vs baseline: 1.5213x; 1.5213x over previous
#include <cuda_runtime.h>
#include <cuda_bf16.h>
#include <math.h>
#include <stdint.h>

#define BB 1024
#define DD 512
#define KK 255
#define LL 256
#define CC 80
#define NGRP 16

// ---- smem layout for k_main (bytes) ----
// xh[buf]: 0 + buf*6144          (128 rows x 48B)
// xl[buf]: 12288 + buf*6144
// wh[buf]: 24576 + buf*3840      (80 rows x 48B)
// wl[buf]: 32256 + buf*3840
// ps:      39936  (128*16 f32)
// bsm:     48128  (16*80 f32)
#define SM_XH 0
#define SM_XL 12288
#define SM_WH 24576
#define SM_WL 32256
#define SM_PS 39936
#define SM_BS 48128
#define SMEM_MAIN 53248

// ---------------- device scratch ----------------
__device__ float g_ne[KK * DD];
__device__ float g_probs[BB * LL];
__device__ float g_partial[NGRP * BB * CC];
__device__ __align__(16) __nv_bfloat16 g_xh[BB * DD];
__device__ __align__(16) __nv_bfloat16 g_xl[BB * DD];
__device__ __align__(16) __nv_bfloat16 g_wh[(size_t)LL * CC * DD];
__device__ __align__(16) __nv_bfloat16 g_wl[(size_t)LL * CC * DD];

// ---------------- helpers ----------------
__device__ __forceinline__ uint32_t s2u(const void* p) {
    uint32_t a;
    asm("{ .reg .u64 t; cvta.to.shared.u64 t, %1; cvt.u32.u64 %0, t; }" : "=r"(a) : "l"(p));
    return a;
}
__device__ __forceinline__ void cp16(uint32_t dst, const void* src) {
    asm volatile("cp.async.cg.shared.global [%0], [%1], 16;" :: "r"(dst), "l"(src));
}
__device__ __forceinline__ void cpcommit() { asm volatile("cp.async.commit_group;" ::: "memory"); }
template <int N> __device__ __forceinline__ void cpwait() {
    asm volatile("cp.async.wait_group %0;" :: "n"(N) : "memory");
}
__device__ __forceinline__ void mma16816(float* c, const uint32_t* a, const uint32_t* b) {
    asm volatile(
        "mma.sync.aligned.m16n8k16.row.col.f32.bf16.bf16.f32 "
        "{%0,%1,%2,%3}, {%4,%5,%6,%7}, {%8,%9}, {%0,%1,%2,%3};"
        : "+f"(c[0]), "+f"(c[1]), "+f"(c[2]), "+f"(c[3])
        : "r"(a[0]), "r"(a[1]), "r"(a[2]), "r"(a[3]), "r"(b[0]), "r"(b[1]));
}

// ---------------- K1: normalize node embeddings ----------------
__global__ void k_norm(const float* __restrict__ ne) {
    int k = blockIdx.x;
    int t = threadIdx.x;
    const float* row = ne + (size_t)k * DD;
    float s = 0.f;
    for (int d = t; d < DD; d += 128) { float v = row[d]; s += v * v; }
    __shared__ float red[4];
    #pragma unroll
    for (int o = 16; o > 0; o >>= 1) s += __shfl_xor_sync(0xffffffffu, s, o);
    if ((t & 31) == 0) red[t >> 5] = s;
    __syncthreads();
    float inv = 1.0f / sqrtf(red[0] + red[1] + red[2] + red[3]);
    for (int d = t; d < DD; d += 128) g_ne[(size_t)k * DD + d] = row[d] * inv;
}

// ---------------- K2: node_sim = sigmoid(x @ ne^T) ----------------
__global__ void k_nodesim(const float* __restrict__ x, float* __restrict__ out_ns) {
    __shared__ float xt[64 * 32];
    __shared__ float nt[64 * 36];
    int row0 = blockIdx.x * 64;
    int col0 = blockIdx.y * 64;
    int tid = threadIdx.x;
    int tx = tid & 15, ty = tid >> 4;
    float acc[4][4] = {};
    for (int dk = 0; dk < 16; ++dk) {
        #pragma unroll
        for (int i = 0; i < 2; ++i) {
            int idx = tid + i * 256;
            int r = idx >> 3, dg = idx & 7;
            float4 v = *(const float4*)(x + (size_t)(row0 + r) * DD + dk * 32 + dg * 4);
            *(float4*)(xt + r * 32 + dg * 4) = v;
        }
        #pragma unroll
        for (int i = 0; i < 2; ++i) {
            int idx = tid + i * 256;
            int r = idx >> 3, dg = idx & 7;
            int kk = col0 + r;
            float4 v = make_float4(0.f, 0.f, 0.f, 0.f);
            if (kk < KK) v = *(const float4*)(g_ne + (size_t)kk * DD + dk * 32 + dg * 4);
            *(float4*)(nt + r * 36 + dg * 4) = v;
        }
        __syncthreads();
        #pragma unroll
        for (int k = 0; k < 32; ++k) {
            float xf[4], nf[4];
            #pragma unroll
            for (int i = 0; i < 4; ++i) xf[i] = xt[(ty * 4 + i) * 32 + k];
            #pragma unroll
            for (int j = 0; j < 4; ++j) nf[j] = nt[(tx + 16 * j) * 36 + k];
            #pragma unroll
            for (int i = 0; i < 4; ++i)
                #pragma unroll
                for (int j = 0; j < 4; ++j) acc[i][j] += xf[i] * nf[j];
        }
        __syncthreads();
    }
    #pragma unroll
    for (int i = 0; i < 4; ++i)
        #pragma unroll
        for (int j = 0; j < 4; ++j) {
            int r = row0 + ty * 4 + i, c = col0 + tx + 16 * j;
            if (c < KK) out_ns[(size_t)r * KK + c] = 1.0f / (1.0f + expf(-acc[i][j]));
        }
}

// ---------------- K3: leaf probabilities ----------------
__global__ void k_probs(const float* __restrict__ ns) {
    int b = blockIdx.x;
    int leaf = threadIdx.x;
    __shared__ float s[KK];
    if (leaf < KK) s[leaf] = ns[(size_t)b * KK + leaf];
    __syncthreads();
    float p = 1.0f; int node = 0;
    #pragma unroll
    for (int d = 0; d < 8; ++d) {
        int bit = (leaf >> (7 - d)) & 1;
        float v = s[node];
        p *= bit ? (1.0f - v) : v;
        node = 2 * node + 1 + bit;
    }
    g_probs[(size_t)b * LL + leaf] = p;
}

// ---------------- conversion: fp32 -> bf16 hi/lo, row-major ----------------
__device__ __forceinline__ void split8(const float* src, __nv_bfloat16* dh, __nv_bfloat16* dl) {
    float4 a = *(const float4*)src;
    float4 b = *(const float4*)(src + 4);
    float v[8] = {a.x, a.y, a.z, a.w, b.x, b.y, b.z, b.w};
    unsigned short hb[8], lb[8];
    #pragma unroll
    for (int i = 0; i < 8; ++i) {
        __nv_bfloat16 h = __float2bfloat16_rn(v[i]);
        hb[i] = __bfloat16_as_ushort(h);
        lb[i] = __bfloat16_as_ushort(__float2bfloat16_rn(v[i] - __bfloat162float(h)));
    }
    *(uint4*)dh = make_uint4(((uint32_t)hb[1] << 16) | hb[0], ((uint32_t)hb[3] << 16) | hb[2],
                             ((uint32_t)hb[5] << 16) | hb[4], ((uint32_t)hb[7] << 16) | hb[6]);
    *(uint4*)dl = make_uint4(((uint32_t)lb[1] << 16) | lb[0], ((uint32_t)lb[3] << 16) | lb[2],
                             ((uint32_t)lb[5] << 16) | lb[4], ((uint32_t)lb[7] << 16) | lb[6]);
}
__global__ void k_convW(const float* __restrict__ W) {
    size_t t = (size_t)blockIdx.x * 256 + threadIdx.x;   // 20480*64
    size_t off = t * 8;
    split8(W + off, g_wh + off, g_wl + off);
}
__global__ void k_convX(const float* __restrict__ x) {
    size_t t = (size_t)blockIdx.x * 256 + threadIdx.x;   // 1024*64
    size_t off = t * 8;
    split8(x + off, g_xh + off, g_xl + off);
}

// ---------------- K5: main HMMA kernel ----------------
// grid (8 rowtiles, 16 leaf-groups), 256 threads = 8 warps (4 M x 2 N).
__global__ void __launch_bounds__(256, 1) k_main(const float* __restrict__ bias) {
    extern __shared__ char smem[];
    const uint32_t sb = s2u(smem);
    const int tid = threadIdx.x;
    const int rt = blockIdx.x;
    const int grp = blockIdx.y;
    const int wid = tid >> 5;
    const int l = tid & 31;
    const int wm = wid >> 1;          // M offset 32*wm
    const int wn = wid & 1;           // N offset 40*wn
    const int lr = l >> 2, lc = l & 3;

    float* psm = (float*)(smem + SM_PS);
    float* bsm = (float*)(smem + SM_BS);
    for (int j = tid; j < 128 * 16; j += 256)
        psm[j] = g_probs[(size_t)(rt * 128 + (j >> 4)) * LL + grp * 16 + (j & 15)];
    for (int j = tid; j < 16 * CC; j += 256)
        bsm[j] = bias[grp * 16 * CC + j];

    // ---- loader lambda-ish: stage step s into buf (s&1) ----
    auto load_step = [&](int s) {
        int buf = s & 1;
        int leaf = grp * 16 + (s >> 5);
        int ks = s & 31;
        #pragma unroll
        for (int j = 0; j < 4; ++j) {
            int idx = tid + j * 256;
            if (idx < 832) {
                if (idx < 512) {
                    int part = idx >> 8;              // 0 hi 1 lo
                    int r = (idx & 255) >> 1, h = idx & 1;
                    const __nv_bfloat16* src =
                        (part ? g_xl : g_xh) + (size_t)(rt * 128 + r) * DD + ks * 16 + h * 8;
                    cp16(sb + (part ? SM_XL : SM_XH) + buf * 6144 + r * 48 + h * 16, src);
                } else {
                    int rel = idx - 512;
                    int part = rel >= 160;
                    if (part) rel -= 160;
                    int r = rel >> 1, h = rel & 1;
                    const __nv_bfloat16* src =
                        (part ? g_wl : g_wh) + ((size_t)leaf * CC + r) * DD + ks * 16 + h * 8;
                    cp16(sb + (part ? SM_WL : SM_WH) + buf * 3840 + r * 48 + h * 16, src);
                }
            }
        }
        cpcommit();
    };

    float acc[2][5][4] = {};
    float per[2][5][4] = {};

    __syncthreads();          // psm/bsm visible
    load_step(0);

    for (int s = 0; s < 512; ++s) {
        if (s + 1 < 512) { load_step(s + 1); cpwait<1>(); }
        else cpwait<0>();
        __syncthreads();

        int buf = s & 1;
        const uint32_t* XH = (const uint32_t*)(smem + SM_XH + buf * 6144);
        const uint32_t* XL = (const uint32_t*)(smem + SM_XL + buf * 6144);
        const uint32_t* WH = (const uint32_t*)(smem + SM_WH + buf * 3840);
        const uint32_t* WL = (const uint32_t*)(smem + SM_WL + buf * 3840);

        uint32_t ah[2][4], al[2][4], bh[5][2], bl[5][2];
        #pragma unroll
        for (int mt = 0; mt < 2; ++mt) {
            int r0 = (wm * 32 + mt * 16 + lr) * 12;
            ah[mt][0] = XH[r0 + lc];       ah[mt][1] = XH[r0 + 96 + lc];
            ah[mt][2] = XH[r0 + 4 + lc];   ah[mt][3] = XH[r0 + 100 + lc];
            al[mt][0] = XL[r0 + lc];       al[mt][1] = XL[r0 + 96 + lc];
            al[mt][2] = XL[r0 + 4 + lc];   al[mt][3] = XL[r0 + 100 + lc];
        }
        #pragma unroll
        for (int nt = 0; nt < 5; ++nt) {
            int nr = (wn * 40 + nt * 8 + lr) * 12;
            bh[nt][0] = WH[nr + lc];  bh[nt][1] = WH[nr + 4 + lc];
            bl[nt][0] = WL[nr + lc];  bl[nt][1] = WL[nr + 4 + lc];
        }
        #pragma unroll
        for (int mt = 0; mt < 2; ++mt)
            #pragma unroll
            for (int nt = 0; nt < 5; ++nt) {
                mma16816(acc[mt][nt], ah[mt], bh[nt]);
                mma16816(acc[mt][nt], ah[mt], bl[nt]);
                mma16816(acc[mt][nt], al[mt], bh[nt]);
            }

        if ((s & 31) == 31) {
            int i = s >> 5;   // leaf index in group
            #pragma unroll
            for (int mt = 0; mt < 2; ++mt) {
                int r0 = wm * 32 + mt * 16 + lr;
                float p0 = psm[r0 * 16 + i];
                float p1 = psm[(r0 + 8) * 16 + i];
                #pragma unroll
                for (int nt = 0; nt < 5; ++nt) {
                    int c0 = wn * 40 + nt * 8 + lc * 2;
                    float b0 = bsm[i * CC + c0], b1 = bsm[i * CC + c0 + 1];
                    per[mt][nt][0] = fmaf(p0, acc[mt][nt][0] + b0, per[mt][nt][0]);
                    per[mt][nt][1] = fmaf(p0, acc[mt][nt][1] + b1, per[mt][nt][1]);
                    per[mt][nt][2] = fmaf(p1, acc[mt][nt][2] + b0, per[mt][nt][2]);
                    per[mt][nt][3] = fmaf(p1, acc[mt][nt][3] + b1, per[mt][nt][3]);
                    acc[mt][nt][0] = acc[mt][nt][1] = acc[mt][nt][2] = acc[mt][nt][3] = 0.f;
                }
            }
        }
        __syncthreads();
    }

    float* base = g_partial + (size_t)grp * BB * CC;
    #pragma unroll
    for (int mt = 0; mt < 2; ++mt) {
        int r0 = rt * 128 + wm * 32 + mt * 16 + lr;
        #pragma unroll
        for (int nt = 0; nt < 5; ++nt) {
            int c0 = wn * 40 + nt * 8 + lc * 2;
            *(float2*)(base + (size_t)r0 * CC + c0) = make_float2(per[mt][nt][0], per[mt][nt][1]);
            *(float2*)(base + (size_t)(r0 + 8) * CC + c0) = make_float2(per[mt][nt][2], per[mt][nt][3]);
        }
    }
}

// ---------------- K6: reduce partials ----------------
__global__ void k_reduce(float* __restrict__ out) {
    int idx = blockIdx.x * 256 + threadIdx.x;
    float s = 0.f;
    #pragma unroll
    for (int g = 0; g < NGRP; ++g)
        s += g_partial[(size_t)g * BB * CC + idx];
    out[idx] = s;
}

// ---------------- launch ----------------
extern "C" void kernel_launch(void* const* d_in, const int* in_sizes, int n_in,
                              void* d_out, int out_size) {
    const float* x    = (const float*)d_in[0];
    const float* ne   = (const float*)d_in[1];
    const float* W    = (const float*)d_in[2];
    const float* bias = (const float*)d_in[3];

    float* out1 = (float*)d_out;
    float* ns   = (float*)d_out + BB * CC;

    static int configured = 0;
    cudaFuncSetAttribute(k_main, cudaFuncAttributeMaxDynamicSharedMemorySize, SMEM_MAIN);
    (void)configured;

    k_norm<<<KK, 128>>>(ne);
    dim3 g2(BB / 64, 4);
    k_nodesim<<<g2, 256>>>(x, ns);
    k_probs<<<BB, 256>>>(ns);
    k_convW<<<5120, 256>>>(W);
    k_convX<<<256, 256>>>(x);
    dim3 g5(8, NGRP);
    k_main<<<g5, 256, SMEM_MAIN>>>(bias);
    k_reduce<<<(BB * CC) / 256, 256>>>(out1);
}

// round 4
// speedup vs baseline: 2.7819x; 1.8286x over previous
#include <cuda_runtime.h>
#include <cuda_bf16.h>
#include <math.h>
#include <stdint.h>

#define BB 1024
#define DD 512
#define KK 255
#define LL 256
#define CC 80
#define NGRP 16

#define WCH 11520      // W chunk bytes per part: 80 rows x 144B
#define XCH 18432      // X chunk bytes per part: 128 rows x 144B

// ---- smem layout (bytes) ----
#define SM_X   0                     // 2 bufs x 2 parts x 18432 = 73728
#define SM_W   73728                 // 3 bufs x 2 parts x 11520 = 69120
#define SM_PS  142848                // 128*17*4 = 8704
#define SM_BS  151552                // 16*80*4 = 5120
#define SM_MB  156672                // mbarriers (80B)
#define SMEM_MAIN 156800

// ---------------- device scratch ----------------
__device__ float g_ne[KK * DD];
__device__ float g_probs[BB * LL];
__device__ float g_partial[NGRP * BB * CC];
__device__ __align__(16) uint8_t g_wb[(size_t)LL * 8 * 2 * WCH];  // [leaf][ks][part][80x144B]
__device__ __align__(16) uint8_t g_xb[(size_t)8 * 8 * 2 * XCH];   // [rt][ks][part][128x144B]

// ---------------- helpers ----------------
__device__ __forceinline__ uint32_t s2u(const void* p) {
    uint32_t a;
    asm("{ .reg .u64 t; cvta.to.shared.u64 t, %1; cvt.u32.u64 %0, t; }" : "=r"(a) : "l"(p));
    return a;
}
#define MBINIT(m, c)  asm volatile("mbarrier.init.shared.b64 [%0], %1;" :: "r"(m), "r"(c) : "memory")
#define MBEXPECT(m, b) asm volatile("mbarrier.arrive.expect_tx.shared.b64 _, [%0], %1;" :: "r"(m), "r"(b) : "memory")
#define MBARRIVE(m)   asm volatile("mbarrier.arrive.shared.b64 _, [%0];" :: "r"(m) : "memory")
__device__ __forceinline__ void mbwait(uint32_t m, uint32_t ph) {
    asm volatile(
        "{\n .reg .pred P;\n"
        "LW_%=:\n mbarrier.try_wait.parity.acquire.cta.shared::cta.b64 P, [%0], %1, 0x989680;\n"
        " @P bra LD_%=;\n bra LW_%=;\nLD_%=:\n}"
        :: "r"(m), "r"(ph) : "memory");
}
#define BULK(dst, src, sz, mb) \
    asm volatile("cp.async.bulk.shared::cta.global.mbarrier::complete_tx::bytes [%0], [%1], %2, [%3];" \
                 :: "r"(dst), "l"(src), "r"(sz), "r"(mb) : "memory")

__device__ __forceinline__ void ldsm4(uint32_t* r, uint32_t a) {
    asm volatile("ldmatrix.sync.aligned.m8n8.x4.shared.b16 {%0,%1,%2,%3}, [%4];"
        : "=r"(r[0]), "=r"(r[1]), "=r"(r[2]), "=r"(r[3]) : "r"(a));
}
__device__ __forceinline__ void ldsm2(uint32_t* r, uint32_t a) {
    asm volatile("ldmatrix.sync.aligned.m8n8.x2.shared.b16 {%0,%1}, [%2];"
        : "=r"(r[0]), "=r"(r[1]) : "r"(a));
}
__device__ __forceinline__ void mma16816(float* c, const uint32_t* a, const uint32_t* b) {
    asm volatile(
        "mma.sync.aligned.m16n8k16.row.col.f32.bf16.bf16.f32 "
        "{%0,%1,%2,%3}, {%4,%5,%6,%7}, {%8,%9}, {%0,%1,%2,%3};"
        : "+f"(c[0]), "+f"(c[1]), "+f"(c[2]), "+f"(c[3])
        : "r"(a[0]), "r"(a[1]), "r"(a[2]), "r"(a[3]), "r"(b[0]), "r"(b[1]));
}

// ---------------- K1: normalize node embeddings ----------------
__global__ void k_norm(const float* __restrict__ ne) {
    int k = blockIdx.x;
    int t = threadIdx.x;
    const float* row = ne + (size_t)k * DD;
    float s = 0.f;
    for (int d = t; d < DD; d += 128) { float v = row[d]; s += v * v; }
    __shared__ float red[4];
    #pragma unroll
    for (int o = 16; o > 0; o >>= 1) s += __shfl_xor_sync(0xffffffffu, s, o);
    if ((t & 31) == 0) red[t >> 5] = s;
    __syncthreads();
    float inv = 1.0f / sqrtf(red[0] + red[1] + red[2] + red[3]);
    for (int d = t; d < DD; d += 128) g_ne[(size_t)k * DD + d] = row[d] * inv;
}

// ---------------- K2: node_sim = sigmoid(x @ ne^T) ----------------
__global__ void k_nodesim(const float* __restrict__ x, float* __restrict__ out_ns) {
    __shared__ float xt[64 * 32];
    __shared__ float nt[64 * 36];
    int row0 = blockIdx.x * 64;
    int col0 = blockIdx.y * 64;
    int tid = threadIdx.x;
    int tx = tid & 15, ty = tid >> 4;
    float acc[4][4] = {};
    for (int dk = 0; dk < 16; ++dk) {
        #pragma unroll
        for (int i = 0; i < 2; ++i) {
            int idx = tid + i * 256;
            int r = idx >> 3, dg = idx & 7;
            float4 v = *(const float4*)(x + (size_t)(row0 + r) * DD + dk * 32 + dg * 4);
            *(float4*)(xt + r * 32 + dg * 4) = v;
        }
        #pragma unroll
        for (int i = 0; i < 2; ++i) {
            int idx = tid + i * 256;
            int r = idx >> 3, dg = idx & 7;
            int kk = col0 + r;
            float4 v = make_float4(0.f, 0.f, 0.f, 0.f);
            if (kk < KK) v = *(const float4*)(g_ne + (size_t)kk * DD + dk * 32 + dg * 4);
            *(float4*)(nt + r * 36 + dg * 4) = v;
        }
        __syncthreads();
        #pragma unroll
        for (int k = 0; k < 32; ++k) {
            float xf[4], nf[4];
            #pragma unroll
            for (int i = 0; i < 4; ++i) xf[i] = xt[(ty * 4 + i) * 32 + k];
            #pragma unroll
            for (int j = 0; j < 4; ++j) nf[j] = nt[(tx + 16 * j) * 36 + k];
            #pragma unroll
            for (int i = 0; i < 4; ++i)
                #pragma unroll
                for (int j = 0; j < 4; ++j) acc[i][j] += xf[i] * nf[j];
        }
        __syncthreads();
    }
    #pragma unroll
    for (int i = 0; i < 4; ++i)
        #pragma unroll
        for (int j = 0; j < 4; ++j) {
            int r = row0 + ty * 4 + i, c = col0 + tx + 16 * j;
            if (c < KK) out_ns[(size_t)r * KK + c] = 1.0f / (1.0f + expf(-acc[i][j]));
        }
}

// ---------------- K3: leaf probabilities ----------------
__global__ void k_probs(const float* __restrict__ ns) {
    int b = blockIdx.x;
    int leaf = threadIdx.x;
    __shared__ float s[KK];
    if (leaf < KK) s[leaf] = ns[(size_t)b * KK + leaf];
    __syncthreads();
    float p = 1.0f; int node = 0;
    #pragma unroll
    for (int d = 0; d < 8; ++d) {
        int bit = (leaf >> (7 - d)) & 1;
        float v = s[node];
        p *= bit ? (1.0f - v) : v;
        node = 2 * node + 1 + bit;
    }
    g_probs[(size_t)b * LL + leaf] = p;
}

// ---------------- conversion helpers ----------------
__device__ __forceinline__ void split8u(const float* src, uint4& HI, uint4& LO) {
    float4 a = *(const float4*)src;
    float4 b = *(const float4*)(src + 4);
    float v[8] = {a.x, a.y, a.z, a.w, b.x, b.y, b.z, b.w};
    unsigned short hb[8], lb[8];
    #pragma unroll
    for (int i = 0; i < 8; ++i) {
        __nv_bfloat16 h = __float2bfloat16_rn(v[i]);
        hb[i] = __bfloat16_as_ushort(h);
        lb[i] = __bfloat16_as_ushort(__float2bfloat16_rn(v[i] - __bfloat162float(h)));
    }
    HI = make_uint4(((uint32_t)hb[1] << 16) | hb[0], ((uint32_t)hb[3] << 16) | hb[2],
                    ((uint32_t)hb[5] << 16) | hb[4], ((uint32_t)hb[7] << 16) | hb[6]);
    LO = make_uint4(((uint32_t)lb[1] << 16) | lb[0], ((uint32_t)lb[3] << 16) | lb[2],
                    ((uint32_t)lb[5] << 16) | lb[4], ((uint32_t)lb[7] << 16) | lb[6]);
}

// W[l*80+n][512] -> g_wb[(leaf*8+ks)*2+part][n*144 + k*2], padded rows
__global__ void k_convW(const float* __restrict__ W) {
    int t = blockIdx.x * 256 + threadIdx.x;      // 20480*64
    int row = t >> 6;
    int kg = t & 63;
    int leaf = row / 80, n = row - leaf * 80;
    int ks = kg >> 3, k8 = kg & 7;
    uint4 HI, LO;
    split8u(W + (size_t)row * 512 + kg * 8, HI, LO);
    uint8_t* dst = g_wb + (size_t)(leaf * 8 + ks) * 2 * WCH + n * 144 + k8 * 16;
    *(uint4*)dst = HI;
    *(uint4*)(dst + WCH) = LO;
}
__global__ void k_convX(const float* __restrict__ x) {
    int t = blockIdx.x * 256 + threadIdx.x;      // 1024*64
    int row = t >> 6;
    int kg = t & 63;
    int rt = row >> 7, r = row & 127;
    int ks = kg >> 3, k8 = kg & 7;
    uint4 HI, LO;
    split8u(x + (size_t)row * 512 + kg * 8, HI, LO);
    uint8_t* dst = g_xb + (size_t)(rt * 8 + ks) * 2 * XCH + r * 144 + k8 * 16;
    *(uint4*)dst = HI;
    *(uint4*)(dst + XCH) = LO;
}

// ---------------- K5: main HMMA kernel ----------------
// grid (8 rowtiles, 16 leaf-groups), 256 threads = 8 warps (4 M x 2 N).
// Stage s (0..127): ks = s>>4 (k-chunk of 64), leaf = s&15.
__global__ void __launch_bounds__(256, 1) k_main(const float* __restrict__ bias) {
    extern __shared__ char smem[];
    const uint32_t sb = s2u(smem);
    const int tid = threadIdx.x;
    const int rt = blockIdx.x, grp = blockIdx.y;
    const int wid = tid >> 5, lane = tid & 31;
    const int wm = wid >> 1, wn = wid & 1;
    const int lr = lane >> 2, lc = lane & 3;

    const uint32_t MB = sb + SM_MB;
    #define WFULL(b)  (MB + (b) * 8)
    #define WEMPTY(b) (MB + 24 + (b) * 8)
    #define XFULL(b)  (MB + 48 + (b) * 8)
    #define XEMPTY(b) (MB + 64 + (b) * 8)

    if (tid == 0) {
        for (int b = 0; b < 3; ++b) { MBINIT(WFULL(b), 1); MBINIT(WEMPTY(b), 8); }
        for (int b = 0; b < 2; ++b) { MBINIT(XFULL(b), 1); MBINIT(XEMPTY(b), 8); }
    }
    float* psm = (float*)(smem + SM_PS);
    float* bsm = (float*)(smem + SM_BS);
    for (int j = tid; j < 128 * 16; j += 256) {
        int r = j >> 4, l = j & 15;
        psm[r * 17 + l] = g_probs[(size_t)(rt * 128 + r) * LL + grp * 16 + l];
    }
    for (int j = tid; j < 16 * CC; j += 256) bsm[j] = bias[grp * 16 * CC + j];
    __syncthreads();

    // prologue: W stages 0,1 ; X ks 0
    if (tid == 0) {
        #pragma unroll
        for (int s = 0; s < 2; ++s) {
            MBEXPECT(WFULL(s), 2 * WCH);
            BULK(sb + SM_W + s * (2 * WCH),
                 g_wb + (size_t)((grp * 16 + s) * 8 + 0) * 2 * WCH, 2 * WCH, WFULL(s));
        }
        MBEXPECT(XFULL(0), 2 * XCH);
        BULK(sb + SM_X, g_xb + (size_t)(rt * 8 + 0) * 2 * XCH, 2 * XCH, XFULL(0));
    }

    // per-thread invariant ldmatrix offsets (bytes within part)
    const uint32_t aoff0 = (uint32_t)(wm * 32 + ((lane >> 3) & 1) * 8 + (lane & 7)) * 144
                           + ((lane >> 4) & 1) * 16;
    const uint32_t aoff1 = aoff0 + 16 * 144;
    const uint32_t boff0 = (uint32_t)(wn * 40 + ((lane >> 4) & 1) * 8 + (lane & 7)) * 144
                           + ((lane >> 3) & 1) * 16;
    const uint32_t boff1 = boff0 + 16 * 144;
    const int l16 = lane & 15;
    const uint32_t boff2 = (uint32_t)(wn * 40 + 32 + (l16 & 7)) * 144 + ((l16 >> 3) & 1) * 16;

    float per[2][5][4] = {};
    int cwf[3] = {0, 0, 0}, cxf[2] = {0, 0};
    int pwe[3] = {0, 0, 0}, pxe[2] = {0, 0};

    for (int s = 0; s < 128; ++s) {
        const int b = s % 3;
        const int ks = s >> 4, leaf = s & 15;
        const int xb = ks & 1;

        if (tid == 0) {
            int sn = s + 2;
            if (sn < 128) {
                int bn = sn % 3;
                if (sn >= 3) { mbwait(WEMPTY(bn), pwe[bn] & 1); pwe[bn]++; }
                MBEXPECT(WFULL(bn), 2 * WCH);
                int lf = grp * 16 + (sn & 15), kn = sn >> 4;
                BULK(sb + SM_W + bn * (2 * WCH),
                     g_wb + (size_t)(lf * 8 + kn) * 2 * WCH, 2 * WCH, WFULL(bn));
            }
            if (leaf == 8 && ks + 1 < 8) {
                int kn = ks + 1, xbn = kn & 1;
                if (kn >= 2) { mbwait(XEMPTY(xbn), pxe[xbn] & 1); pxe[xbn]++; }
                MBEXPECT(XFULL(xbn), 2 * XCH);
                BULK(sb + SM_X + xbn * (2 * XCH),
                     g_xb + (size_t)(rt * 8 + kn) * 2 * XCH, 2 * XCH, XFULL(xbn));
            }
        }

        mbwait(WFULL(b), cwf[b] & 1); cwf[b]++;
        if (leaf == 0) { mbwait(XFULL(xb), cxf[xb] & 1); cxf[xb]++; }

        float acc[2][5][4];
        if (ks == 0) {
            #pragma unroll
            for (int nt = 0; nt < 5; ++nt) {
                int c0 = wn * 40 + nt * 8 + lc * 2;
                float b0 = bsm[leaf * CC + c0], b1 = bsm[leaf * CC + c0 + 1];
                #pragma unroll
                for (int mt = 0; mt < 2; ++mt) {
                    acc[mt][nt][0] = b0; acc[mt][nt][1] = b1;
                    acc[mt][nt][2] = b0; acc[mt][nt][3] = b1;
                }
            }
        } else {
            #pragma unroll
            for (int mt = 0; mt < 2; ++mt)
                #pragma unroll
                for (int nt = 0; nt < 5; ++nt)
                    acc[mt][nt][0] = acc[mt][nt][1] = acc[mt][nt][2] = acc[mt][nt][3] = 0.f;
        }

        const uint32_t xh = sb + SM_X + xb * (2 * XCH);
        const uint32_t xl = xh + XCH;
        const uint32_t wh = sb + SM_W + b * (2 * WCH);
        const uint32_t wl = wh + WCH;

        #pragma unroll
        for (int kc = 0; kc < 4; ++kc) {
            const int ko = kc * 32;
            uint32_t ah[2][4], al[2][4], bh[5][2], bl[5][2];
            ldsm4(ah[0], xh + aoff0 + ko);
            ldsm4(ah[1], xh + aoff1 + ko);
            ldsm4(al[0], xl + aoff0 + ko);
            ldsm4(al[1], xl + aoff1 + ko);
            ldsm4(&bh[0][0], wh + boff0 + ko);
            ldsm4(&bh[2][0], wh + boff1 + ko);
            ldsm2(&bh[4][0], wh + boff2 + ko);
            ldsm4(&bl[0][0], wl + boff0 + ko);
            ldsm4(&bl[2][0], wl + boff1 + ko);
            ldsm2(&bl[4][0], wl + boff2 + ko);
            #pragma unroll
            for (int mt = 0; mt < 2; ++mt)
                #pragma unroll
                for (int nt = 0; nt < 5; ++nt) {
                    mma16816(acc[mt][nt], ah[mt], bh[nt]);
                    mma16816(acc[mt][nt], ah[mt], bl[nt]);
                    mma16816(acc[mt][nt], al[mt], bh[nt]);
                }
        }

        // fold probability (linearity: out = sum over chunks of p * chunk)
        #pragma unroll
        for (int mt = 0; mt < 2; ++mt) {
            float p0 = psm[(wm * 32 + mt * 16 + lr) * 17 + leaf];
            float p1 = psm[(wm * 32 + mt * 16 + 8 + lr) * 17 + leaf];
            #pragma unroll
            for (int nt = 0; nt < 5; ++nt) {
                per[mt][nt][0] = fmaf(p0, acc[mt][nt][0], per[mt][nt][0]);
                per[mt][nt][1] = fmaf(p0, acc[mt][nt][1], per[mt][nt][1]);
                per[mt][nt][2] = fmaf(p1, acc[mt][nt][2], per[mt][nt][2]);
                per[mt][nt][3] = fmaf(p1, acc[mt][nt][3], per[mt][nt][3]);
            }
        }

        if (lane == 0) {
            MBARRIVE(WEMPTY(b));
            if (leaf == 15) MBARRIVE(XEMPTY(xb));
        }
    }

    float* base = g_partial + (size_t)grp * BB * CC;
    #pragma unroll
    for (int mt = 0; mt < 2; ++mt) {
        int r0 = rt * 128 + wm * 32 + mt * 16 + lr;
        #pragma unroll
        for (int nt = 0; nt < 5; ++nt) {
            int c0 = wn * 40 + nt * 8 + lc * 2;
            *(float2*)(base + (size_t)r0 * CC + c0) = make_float2(per[mt][nt][0], per[mt][nt][1]);
            *(float2*)(base + (size_t)(r0 + 8) * CC + c0) = make_float2(per[mt][nt][2], per[mt][nt][3]);
        }
    }
}

// ---------------- K6: reduce partials ----------------
__global__ void k_reduce(float* __restrict__ out) {
    int idx = blockIdx.x * 256 + threadIdx.x;
    float s = 0.f;
    #pragma unroll
    for (int g = 0; g < NGRP; ++g)
        s += g_partial[(size_t)g * BB * CC + idx];
    out[idx] = s;
}

// ---------------- launch ----------------
extern "C" void kernel_launch(void* const* d_in, const int* in_sizes, int n_in,
                              void* d_out, int out_size) {
    const float* x    = (const float*)d_in[0];
    const float* ne   = (const float*)d_in[1];
    const float* W    = (const float*)d_in[2];
    const float* bias = (const float*)d_in[3];

    float* out1 = (float*)d_out;
    float* ns   = (float*)d_out + BB * CC;

    cudaFuncSetAttribute(k_main, cudaFuncAttributeMaxDynamicSharedMemorySize, SMEM_MAIN);

    k_norm<<<KK, 128>>>(ne);
    dim3 g2(BB / 64, 4);
    k_nodesim<<<g2, 256>>>(x, ns);
    k_probs<<<BB, 256>>>(ns);
    k_convW<<<5120, 256>>>(W);
    k_convX<<<256, 256>>>(x);
    dim3 g5(8, NGRP);
    k_main<<<g5, 256, SMEM_MAIN>>>(bias);
    k_reduce<<<(BB * CC) / 256, 256>>>(out1);
}